// round 7
// baseline (speedup 1.0000x reference)
#include <cuda_runtime.h>

#define Ww 112
#define NP (112*112)
#define NCH 64
#define RS 29                  // shared row stride in float4 units (odd mod 8)
#define SMSZ (112*RS)          // 3248 float4 = 51968 B (dynamic shared)

__device__ __forceinline__ float rcpa(float x) {
    float y; asm("rcp.approx.f32 %0, %1;" : "=f"(y) : "f"(x)); return y;
}

__device__ __forceinline__ void unp(float4 q, float* r) {
    r[0]=q.x; r[1]=q.y; r[2]=q.z; r[3]=q.w;
}

// 4 outputs with ONE MUFU.RCP: r = 1/(d0 d1 d2 d3), recover each 1/di.
__device__ __forceinline__ float4 norm4(const float* n, const float* d,
                                        float wgt, float bs) {
    const float d01 = d[0]*d[1], d23 = d[2]*d[3];
    const float r   = rcpa(d01*d23);
    const float r01 = r*d23, r23 = r*d01;
    float4 o;
    o.x = fmaf(wgt*n[0], r01*d[1], bs);
    o.y = fmaf(wgt*n[1], r01*d[0], bs);
    o.z = fmaf(wgt*n[2], r23*d[3], bs);
    o.w = fmaf(wgt*n[3], r23*d[2], bs);
    return o;
}

// den from vertical sums t via sliding 5-sum (uniform ck), fold sigma^p
template<int TW,int MAXS>
__device__ __forceinline__ void den_from_t(const float* __restrict__ t,
                                           const int* __restrict__ off,
                                           float w25, float sp,
                                           float* __restrict__ den) {
    float h[MAXS+1];
    h[0] = ((t[0]+t[1]) + (t[2]+t[3])) + t[4];
#pragma unroll
    for (int s = 1; s <= MAXS; s++)
        h[s] = h[s-1] - t[s-1] + t[s+4];
#pragma unroll
    for (int j = 0; j < 8; j++)
        den[j] = fmaf(w25, h[off[j]], sp);
}

// full per-row den rebuild (modes 1 and 2 fallback)
template<int NG,int TLO,int TW,int MAXS>
__device__ __forceinline__ void den_row(const float4* __restrict__ s4,
                                        int lybase, int gb, int mode,
                                        const float* __restrict__ rk,
                                        const float* __restrict__ ck,
                                        const float* __restrict__ kerg,
                                        float sp,
                                        const int* __restrict__ off,
                                        float* __restrict__ den) {
    if (mode == 1) {
        float tv[TW];
#pragma unroll
        for (int rr = 0; rr < 5; rr++) {
            const float4* p = s4 + (lybase + rr) * RS + gb;
            float rv[16];
            unp(p[0], rv); unp(p[1], rv+4); unp(p[2], rv+8);
            if (NG == 4) unp(p[3], rv+12);
            const float w = rk[rr];
            if (rr == 0) {
#pragma unroll
                for (int k = 0; k < TW; k++) tv[k] = w * rv[TLO+k];
            } else {
#pragma unroll
                for (int k = 0; k < TW; k++) tv[k] = fmaf(w, rv[TLO+k], tv[k]);
            }
        }
#pragma unroll
        for (int j = 0; j < 8; j++) {
            float a = 0.0f;
#pragma unroll
            for (int t = 0; t < 5; t++)
                a = fmaf(ck[t], tv[off[j]+t], a);
            den[j] = sp + a;
        }
    } else {
        float a[8];
#pragma unroll
        for (int j = 0; j < 8; j++) a[j] = 0.0f;
#pragma unroll
        for (int rr = 0; rr < 5; rr++) {
            const float4* p = s4 + (lybase + rr) * RS + gb;
            float rv[16];
            unp(p[0], rv); unp(p[1], rv+4); unp(p[2], rv+8);
            if (NG == 4) unp(p[3], rv+12);
#pragma unroll
            for (int t = 0; t < 5; t++) {
                const float w = __ldg(kerg + rr*5 + t);
#pragma unroll
                for (int j = 0; j < 8; j++)
                    a[j] = fmaf(w, rv[TLO+off[j]+t], a[j]);
            }
        }
#pragma unroll
        for (int j = 0; j < 8; j++) den[j] = sp + a[j];
    }
}

// One thread walks a 7-row y-strip of an 8-wide x-group, sliding the
// vertical sum t (mode 0) so each new row costs 2 row-loads instead of 5.
template<int NG,int TLO,int TW,int MAXS,int NBG,
         int O0,int O1,int O2,int O3,int O4,int O5,int O6,int O7>
__device__ __forceinline__ void strip_run(
    const float4* __restrict__ s4, int gb, int strip, int mode,
    const float* __restrict__ rk, const float* __restrict__ ck,
    float w25, const float* __restrict__ kerg,
    float sp, float wgt, float bs,
    float* __restrict__ po, int xbase)
{
    const int off[8] = {O0,O1,O2,O3,O4,O5,O6,O7};
    const int y0 = strip * 7;
    int cy = min(max(y0, 2), 109);

    float t[TW];
    float den[8];

    if (mode == 0) {
        // initial build: plain sum of rows cy-2..cy+2 (rk == 1)
        {
            const float4* p = s4 + (cy - 2) * RS + gb;
            float rv[16];
            unp(p[0], rv); unp(p[1], rv+4); unp(p[2], rv+8);
            if (NG == 4) unp(p[3], rv+12);
#pragma unroll
            for (int k = 0; k < TW; k++) t[k] = rv[TLO+k];
        }
#pragma unroll
        for (int rr = 1; rr < 5; rr++) {
            const float4* p = s4 + (cy - 2 + rr) * RS + gb;
            float rv[16];
            unp(p[0], rv); unp(p[1], rv+4); unp(p[2], rv+8);
            if (NG == 4) unp(p[3], rv+12);
#pragma unroll
            for (int k = 0; k < TW; k++) t[k] += rv[TLO+k];
        }
        den_from_t<TW,MAXS>(t, off, w25, sp, den);
    }

#pragma unroll 1
    for (int y = y0; y < y0 + 7; y++) {
        const int cyn = min(max(y, 2), 109);
        if (mode == 0) {
            if (cyn != cy) {
                cy = cyn;
                const float4* pn = s4 + (cy + 2) * RS + gb;   // entering row
                const float4* pd = s4 + (cy - 3) * RS + gb;   // leaving row
                float rn[16], rd[16];
                unp(pn[0], rn); unp(pn[1], rn+4); unp(pn[2], rn+8);
                unp(pd[0], rd); unp(pd[1], rd+4); unp(pd[2], rd+8);
                if (NG == 4) { unp(pn[3], rn+12); unp(pd[3], rd+12); }
#pragma unroll
                for (int k = 0; k < TW; k++)
                    t[k] += rn[TLO+k] - rd[TLO+k];
                den_from_t<TW,MAXS>(t, off, w25, sp, den);
            }
        } else {
            den_row<NG,TLO,TW,MAXS>(s4, cyn - 2, gb, mode,
                                    rk, ck, kerg, sp, off, den);
        }

        // numerator xp[y] + normalize + stores
        float n[8];
        const float4* np = s4 + y * RS + gb + NBG;
        unp(np[0], n); unp(np[1], n+4);
        float4* orow = reinterpret_cast<float4*>(po + y * Ww + xbase);
        orow[0] = norm4(n,     den,     wgt, bs);
        orow[1] = norm4(n + 4, den + 4, wgt, bs);
    }
}

__global__ __launch_bounds__(256, 4)
void bionorm_kernel(const float* __restrict__ x,
                    const float* __restrict__ sigma,
                    const float* __restrict__ pow_p,
                    const float* __restrict__ ker,
                    const float* __restrict__ weight,
                    const float* __restrict__ bias,
                    float* __restrict__ out)
{
    extern __shared__ float4 s4[];          // full plane, [112][RS]
    const int plane = blockIdx.x;           // b*C + c
    const int c     = plane & (NCH - 1);

    const float* __restrict__ xin = x + (size_t)plane * NP;
    float* __restrict__ po        = out + (size_t)plane * NP;

    const float p  = pow_p[c];
    const bool  p2 = (p == 2.0f);

    // ---- Phase 1: float4 load + x^p -> shared ----
    const float4* __restrict__ xin4 = reinterpret_cast<const float4*>(xin);
    for (int i = threadIdx.x; i < 112 * 28; i += 256) {
        const int ly = i / 28;
        const int g  = i - ly * 28;
        float4 v = xin4[i];
        float4 rq;
        if (p2) {
            rq.x = v.x*v.x; rq.y = v.y*v.y; rq.z = v.z*v.z; rq.w = v.w*v.w;
        } else {
            rq.x = __powf(v.x, p); rq.y = __powf(v.y, p);
            rq.z = __powf(v.z, p); rq.w = __powf(v.w, p);
        }
        s4[ly * RS + g] = rq;
    }

    // ---- per-channel params: rank-1 / uniform / unit-rk detection ----
    const float* __restrict__ kerg = ker + c * 25;
    float maxa = 0.0f, best = -1.0f; int pi = 0;
#pragma unroll
    for (int i = 0; i < 25; i++) {
        const float a = fabsf(__ldg(kerg + i));
        maxa = fmaxf(maxa, a);
        if (a > best) { best = a; pi = i; }
    }
    const int i0 = pi / 5, j0 = pi - i0 * 5;

    float rk[5], ck[5];
    int mode = 2;
    if (maxa > 0.0f) {
        const float inv = 1.0f / __ldg(kerg + pi);
#pragma unroll
        for (int i = 0; i < 5; i++) rk[i] = __ldg(kerg + i*5 + j0) * inv;
#pragma unroll
        for (int j = 0; j < 5; j++) ck[j] = __ldg(kerg + i0*5 + j);
        bool sep = true;
        const float tol = 1e-6f * maxa;
#pragma unroll
        for (int i = 0; i < 5; i++)
#pragma unroll
            for (int j = 0; j < 5; j++)
                if (fabsf(fmaf(-rk[i], ck[j], __ldg(kerg + i*5 + j))) > tol)
                    sep = false;
        if (sep) {
            // mode 0 needs uniform ck AND unit rk (plain-sum slide)
            bool uni = true;
            const float utol = 1e-6f * fabsf(ck[0]);
#pragma unroll
            for (int j = 1; j < 5; j++)
                if (fabsf(ck[j] - ck[0]) > utol) uni = false;
#pragma unroll
            for (int i = 0; i < 5; i++)
                if (fabsf(rk[i] - 1.0f) > 1e-6f) uni = false;
            mode = uni ? 0 : 1;
        }
    } else {
#pragma unroll
        for (int i = 0; i < 5; i++) { rk[i] = 1.0f; ck[i] = 0.0f; }
        mode = 0;   // zero kernel: uniform with w25 = 0
    }
    const float w25 = ck[0];

    const float sgm = sigma[c];
    const float sp  = p2 ? sgm*sgm : __powf(sgm, p);
    const float wgt = weight[c];
    const float bs  = bias[c];

    __syncthreads();

    // ---- Phase 2: 14 x-groups x 16 y-strips of 7 rows (224 threads) ----
    // lanes within a warp are consecutive strips: row delta 7 -> bank-group
    // delta 29*7 = 3 (mod 8), bijective over 8 lanes -> conflict-free
    const int tid = threadIdx.x;
    if (tid < 224) {
        const int xg    = tid >> 4;
        const int strip = tid & 15;
        if (xg == 0)
            strip_run<3,0,10,5,0, 0,0,0,1,2,3,4,5>(s4, 0,        strip, mode,
                rk, ck, w25, kerg, sp, wgt, bs, po, 0);
        else if (xg == 13)
            strip_run<3,2,10,5,1, 0,1,2,3,4,5,5,5>(s4, 25,       strip, mode,
                rk, ck, w25, kerg, sp, wgt, bs, po, 104);
        else
            strip_run<4,2,12,7,1, 0,1,2,3,4,5,6,7>(s4, 2*xg - 1, strip, mode,
                rk, ck, w25, kerg, sp, wgt, bs, po, xg << 3);
    }
}

extern "C" void kernel_launch(void* const* d_in, const int* in_sizes, int n_in,
                              void* d_out, int out_size)
{
    const float* x      = (const float*)d_in[0];
    const float* sigma  = (const float*)d_in[1];
    const float* pow_p  = (const float*)d_in[2];
    const float* ker    = (const float*)d_in[3];
    const float* weight = (const float*)d_in[4];
    const float* bias   = (const float*)d_in[5];
    float* out = (float*)d_out;

    cudaFuncSetAttribute(bionorm_kernel,
                         cudaFuncAttributeMaxDynamicSharedMemorySize,
                         SMSZ * 16);

    bionorm_kernel<<<32 * NCH, 256, SMSZ * 16>>>(x, sigma, pow_p, ker,
                                                 weight, bias, out);
}